// round 6
// baseline (speedup 1.0000x reference)
#include <cuda_runtime.h>
#include <math.h>
#include <stdint.h>

// ---------------- problem constants ----------------
#define BB   8
#define NN   1024
#define IND  64
#define HIDD 96
#define NEG  0.2f

// ---------------- scratch (device globals) ----------------
__device__ float    g_x[6][BB * NN * HIDD];        // x0..x5
__device__ uint32_t g_hT[BB * HIDD * NN];          // h transposed, tf32: [b][col][n]
__device__ float    g_es[BB * 3 * NN];
__device__ float    g_ed[BB * 3 * NN];
__device__ unsigned g_adjb[NN * NN / 32];
__device__ float    g_gates[BB * 2];
__device__ float    g_poolc[5 * 16 * BB * HIDD];   // [slot][chunk16][b][col]
__device__ float    g_pacc[48 * 1024 * 96];        // split partial acc
__device__ float    g_psum[48 * 1024];             // split partial rowsums

// ---------------- helpers ----------------
__device__ __forceinline__ float warpSum(float v) {
    #pragma unroll
    for (int o = 16; o; o >>= 1) v += __shfl_xor_sync(0xffffffffu, v, o);
    return v;
}
__device__ __forceinline__ float warpMax(float v) {
    #pragma unroll
    for (int o = 16; o; o >>= 1) v = fmaxf(v, __shfl_xor_sync(0xffffffffu, v, o));
    return v;
}
__device__ __forceinline__ float eluf(float x) { return x > 0.f ? x : expm1f(x); }
__device__ __forceinline__ float* bufsel(int id) { return g_x[id]; }

__device__ __forceinline__ uint32_t to_tf32(float f) {
    uint32_t u;
    asm("cvt.rna.tf32.f32 %0, %1;" : "=r"(u) : "f"(f));
    return u;
}
__device__ __forceinline__ void mma_tf32(float* c, uint32_t a0, uint32_t a1,
                                         uint32_t a2, uint32_t a3,
                                         uint32_t b0, uint32_t b1) {
    asm volatile(
        "mma.sync.aligned.m16n8k8.row.col.f32.tf32.tf32.f32 "
        "{%0,%1,%2,%3}, {%4,%5,%6,%7}, {%8,%9}, {%0,%1,%2,%3};"
        : "+f"(c[0]), "+f"(c[1]), "+f"(c[2]), "+f"(c[3])
        : "r"(a0), "r"(a1), "r"(a2), "r"(a3), "r"(b0), "r"(b1));
}

// ---------------- 1. adjacency -> bitmask ----------------
__global__ void k_adjbits(const int* __restrict__ adj) {
    int gw   = (blockIdx.x * blockDim.x + threadIdx.x) >> 5;
    int lane = threadIdx.x & 31;
    unsigned m = __ballot_sync(0xffffffffu, adj[gw * 32 + lane] > 0);
    if (lane == 0) g_adjb[gw] = m;
}

// ---------------- 2. LayerNorm + pre Linear + ELU -> x0 ----------------
__global__ __launch_bounds__(256) void k_ln_pre(
    const float* __restrict__ x, const float* __restrict__ ln_g,
    const float* __restrict__ ln_b, const float* __restrict__ W,
    const float* __restrict__ bias)
{
    __shared__ float Ws[IND * HIDD];
    __shared__ float xs[8][IND];
    int tid = threadIdx.x, warp = tid >> 5, lane = tid & 31;
    for (int i = tid; i < IND * HIDD; i += 256) Ws[i] = W[i];

    int row = blockIdx.x * 8 + warp;
    const float* xr = x + row * IND;
    float v0 = xr[lane], v1 = xr[lane + 32];
    float mu = warpSum(v0 + v1) * (1.f / IND);
    float d0 = v0 - mu, d1 = v1 - mu;
    float var = warpSum(d0 * d0 + d1 * d1) * (1.f / IND);
    float rs = rsqrtf(var + 1e-5f);
    xs[warp][lane]      = d0 * rs * ln_g[lane]      + ln_b[lane];
    xs[warp][lane + 32] = d1 * rs * ln_g[lane + 32] + ln_b[lane + 32];
    __syncthreads();

    float a0 = bias[lane], a1 = bias[lane + 32], a2 = bias[lane + 64];
    #pragma unroll
    for (int d = 0; d < IND; d++) {
        float xv = xs[warp][d];
        a0 += xv * Ws[d * HIDD + lane];
        a1 += xv * Ws[d * HIDD + lane + 32];
        a2 += xv * Ws[d * HIDD + lane + 64];
    }
    float* o = g_x[0] + row * HIDD;
    o[lane] = eluf(a0); o[lane + 32] = eluf(a1); o[lane + 64] = eluf(a2);
}

// ---------------- 3. h = mix(x) @ W via tf32 MMA, es/ed, hT(tf32) store ----------------
#define GH_WS   0
#define GH_TILE 39936
#define GH_AV   (39936 + 25600)
#define GH_SMEM (GH_AV + 768)

__global__ __launch_bounds__(256) void k_gemmh(
    int ia, int ib, int ic, int mode, int gidx,
    const float* __restrict__ W, const float* __restrict__ a_src,
    const float* __restrict__ a_dst, int H)
{
    extern __shared__ char dsm[];
    uint32_t* Ws_u  = (uint32_t*)(dsm + GH_WS);
    uint32_t* in_s  = (uint32_t*)(dsm + GH_TILE);
    float*    out_s = (float*)(dsm + GH_TILE);
    float*    as_s  = (float*)(dsm + GH_AV);
    float*    ad_s  = as_s + 96;

    int tid = threadIdx.x, wid = tid >> 5, lane = tid & 31;
    int g = lane >> 2, tg = lane & 3;
    int row0 = blockIdx.x * 64;
    int b = row0 >> 10, nb = row0 & (NN - 1);

    float c_a = 1.f, c_b = 0.f, c_c = 0.f;
    if (mode == 1) { float gg = g_gates[b * 2 + gidx]; c_a = 1.f - gg; c_b = gg; }
    else if (mode == 2) { c_b = 0.5f * g_gates[b * 2]; c_c = 0.5f * g_gates[b * 2 + 1]; }

    for (int i = tid; i < 96 * 96; i += 256) {
        int r = i / 96, c = i - r * 96;
        Ws_u[r * 104 + c] = to_tf32(W[i]);
    }
    if (tid < 96) { as_s[tid] = a_src[tid]; ad_s[tid] = a_dst[tid]; }

    const float* A  = bufsel(ia) + row0 * HIDD;
    const float* Bp = bufsel(ib) + row0 * HIDD;
    const float* Cp = bufsel(ic) + row0 * HIDD;
    for (int idx = tid; idx < 64 * 96; idx += 256) {
        int r = idx / 96, c = idx - r * 96;
        float v = c_a * A[idx];
        if (mode >= 1) v += c_b * Bp[idx];
        if (mode == 2) v += c_c * Cp[idx];
        in_s[r * 100 + c] = to_tf32(v);
    }
    __syncthreads();

    int mrow = (wid >> 1) * 16;
    int n0 = (wid & 1) * 48;
    float acc[6][4];
    #pragma unroll
    for (int nt = 0; nt < 6; nt++)
        #pragma unroll
        for (int q = 0; q < 4; q++) acc[nt][q] = 0.f;

    #pragma unroll
    for (int kt = 0; kt < 12; kt++) {
        int kl = kt * 8 + tg;
        uint32_t a0 = in_s[(mrow + g) * 100 + kl];
        uint32_t a1 = in_s[(mrow + g + 8) * 100 + kl];
        uint32_t a2 = in_s[(mrow + g) * 100 + kl + 4];
        uint32_t a3 = in_s[(mrow + g + 8) * 100 + kl + 4];
        #pragma unroll
        for (int nt = 0; nt < 6; nt++) {
            uint32_t b0 = Ws_u[kl * 104 + n0 + nt * 8 + g];
            uint32_t b1 = Ws_u[(kl + 4) * 104 + n0 + nt * 8 + g];
            mma_tf32(acc[nt], a0, a1, a2, a3, b0, b1);
        }
    }
    __syncthreads();

    #pragma unroll
    for (int nt = 0; nt < 6; nt++) {
        int col = n0 + nt * 8 + tg * 2;
        out_s[(mrow + g) * 97 + col]         = acc[nt][0];
        out_s[(mrow + g) * 97 + col + 1]     = acc[nt][1];
        out_s[(mrow + g + 8) * 97 + col]     = acc[nt][2];
        out_s[(mrow + g + 8) * 97 + col + 1] = acc[nt][3];
    }
    __syncthreads();

    uint32_t* hT = g_hT + (size_t)b * HIDD * NN;
    int n_loc = tid & 63, dg = tid >> 6;
    #pragma unroll
    for (int t = 0; t < 24; t++) {
        int d = dg * 24 + t;
        hT[(size_t)d * NN + nb + n_loc] = to_tf32(out_s[n_loc * 97 + d]);
    }

    #pragma unroll
    for (int rr = 0; rr < 8; rr++) {
        int r = wid * 8 + rr;
        float v0 = out_s[r * 97 + lane];
        float v1 = out_s[r * 97 + 32 + lane];
        float v2 = out_s[r * 97 + 64 + lane];
        float s0v = v0 * as_s[lane], s1v = v1 * as_s[lane + 32], s2v = v2 * as_s[lane + 64];
        float d0v = v0 * ad_s[lane], d1v = v1 * ad_s[lane + 32], d2v = v2 * ad_s[lane + 64];
        int n = nb + r;
        if (H == 1) {
            float ps = warpSum(s0v + s1v + s2v);
            float pd = warpSum(d0v + d1v + d2v);
            if (lane == 0) { g_es[b * NN + n] = ps; g_ed[b * NN + n] = pd; }
        } else {
            float s0 = warpSum(s0v), s1 = warpSum(s1v), s2 = warpSum(s2v);
            float e0 = warpSum(d0v), e1 = warpSum(d1v), e2 = warpSum(d2v);
            if (lane == 0) {
                g_es[(b * 3 + 0) * NN + n] = s0; g_ed[(b * 3 + 0) * NN + n] = e0;
                g_es[(b * 3 + 1) * NN + n] = s1; g_ed[(b * 3 + 1) * NN + n] = e1;
                g_es[(b * 3 + 2) * NN + n] = s2; g_ed[(b * 3 + 2) * NN + n] = e2;
            }
        }
    }
}

// ---------------- 4. attention aggregation (tf32 mma, j-split partials) ----------------
// grid (16, S, NBH). Writes unnormalized partial out^T + partial rowsums.
template <int D, int S, int NBH>
__global__ __launch_bounds__(256) void k_aggT(int H) {
    constexpr int MT_W = D / 32;
    constexpr int NT_W = 2;

    __shared__ uint32_t hs[D * 36];
    __shared__ float es_s[64], A1s[64], A2s[64];
    __shared__ float eds[32], e1s[32], e2s[32];
    __shared__ unsigned ms[64];
    __shared__ float red[8];

    int tid = threadIdx.x, wid = tid >> 5, lane = tid & 31;
    int g = lane >> 2, tg = lane & 3;
    int mi = wid >> 2, ni = wid & 3;
    int bh = blockIdx.z, sp = blockIdx.y;
    int b = bh / H, head = bh - b * H, hoff = head * D;
    int i0 = blockIdx.x * 64;

    const uint32_t* hTb = g_hT + ((size_t)b * HIDD + hoff) * NN;

    {
        const float4* ed4 = (const float4*)(g_ed + bh * NN);
        float4 vv = ed4[tid];
        float mx = fmaxf(fmaxf(vv.x, vv.y), fmaxf(vv.z, vv.w));
        mx = warpMax(mx);
        if (lane == 0) red[wid] = mx;
    }
    __syncthreads();
    float maxed = fmaxf(fmaxf(fmaxf(red[0], red[1]), fmaxf(red[2], red[3])),
                        fmaxf(fmaxf(red[4], red[5]), fmaxf(red[6], red[7])));
    if (tid < 64) {
        float es = g_es[bh * NN + i0 + tid];
        es_s[tid] = es;
        float t = es + maxed;
        float m = t > 0.f ? t : NEG * t;
        A1s[tid] = __expf(t - m);
        A2s[tid] = __expf(NEG * t - m);
    }
    __syncthreads();

    float esb[NT_W], A1b[NT_W], A2b[NT_W], rs[NT_W];
    int ib_loc[NT_W];
    #pragma unroll
    for (int ntl = 0; ntl < NT_W; ntl++) {
        ib_loc[ntl] = (ni * NT_W + ntl) * 8 + g;
        esb[ntl] = es_s[ib_loc[ntl]];
        A1b[ntl] = A1s[ib_loc[ntl]];
        A2b[ntl] = A2s[ib_loc[ntl]];
        rs[ntl] = 0.f;
    }

    float acc[MT_W][NT_W][4];
    #pragma unroll
    for (int m = 0; m < MT_W; m++)
        #pragma unroll
        for (int n = 0; n < NT_W; n++)
            #pragma unroll
            for (int q = 0; q < 4; q++) acc[m][n][q] = 0.f;

    constexpr int CPS = NN / S / 32;   // chunks per split
    for (int c = sp * CPS; c < (sp + 1) * CPS; c++) {
        int j0 = c * 32;
        __syncthreads();
        #pragma unroll
        for (int it = 0; it < D * 32 / 256; it++) {
            int idx = tid + it * 256;
            int d = idx >> 5, jj = idx & 31;
            hs[d * 36 + jj] = hTb[(size_t)d * NN + j0 + jj];
        }
        if (tid < 32) {
            float e = g_ed[bh * NN + j0 + tid];
            eds[tid] = e;
            float dd = e - maxed;
            e1s[tid] = __expf(dd);
            e2s[tid] = __expf(NEG * dd);
        } else if (tid >= 96 && tid < 160) {
            ms[tid - 96] = g_adjb[(i0 + tid - 96) * 32 + c];
        }
        __syncthreads();

        unsigned msb[NT_W];
        #pragma unroll
        for (int ntl = 0; ntl < NT_W; ntl++) msb[ntl] = ms[ib_loc[ntl]];

        #pragma unroll
        for (int kt = 0; kt < 4; kt++) {
            int jl = kt * 8 + tg, jh = jl + 4;
            float edl = eds[jl], e1l = e1s[jl], e2l = e2s[jl];
            float edh = eds[jh], e1h = e1s[jh], e2h = e2s[jh];
            uint32_t bf0[NT_W], bf1[NT_W];
            #pragma unroll
            for (int ntl = 0; ntl < NT_W; ntl++) {
                float t0 = esb[ntl] + edl;
                float w0 = (t0 > 0.f) ? A1b[ntl] * e1l : A2b[ntl] * e2l;
                w0 = ((msb[ntl] >> jl) & 1u) ? w0 : 0.f;
                float t1 = esb[ntl] + edh;
                float w1 = (t1 > 0.f) ? A1b[ntl] * e1h : A2b[ntl] * e2h;
                w1 = ((msb[ntl] >> jh) & 1u) ? w1 : 0.f;
                if (mi == 0) rs[ntl] += w0 + w1;
                bf0[ntl] = to_tf32(w0);
                bf1[ntl] = to_tf32(w1);
            }
            #pragma unroll
            for (int mt = 0; mt < MT_W; mt++) {
                int dr = mi * (MT_W * 16) + mt * 16 + g;
                uint32_t a0 = hs[dr * 36 + jl];
                uint32_t a1 = hs[(dr + 8) * 36 + jl];
                uint32_t a2 = hs[dr * 36 + jh];
                uint32_t a3 = hs[(dr + 8) * 36 + jh];
                #pragma unroll
                for (int ntl = 0; ntl < NT_W; ntl++)
                    mma_tf32(acc[mt][ntl], a0, a1, a2, a3, bf0[ntl], bf1[ntl]);
            }
        }
    }

    if (mi == 0) {
        #pragma unroll
        for (int ntl = 0; ntl < NT_W; ntl++) {
            float r = rs[ntl];
            r += __shfl_xor_sync(0xffffffffu, r, 1);
            r += __shfl_xor_sync(0xffffffffu, r, 2);
            if (tg == 0) g_psum[(size_t)(sp * NBH + bh) * NN + i0 + ib_loc[ntl]] = r;
        }
    }

    float* pa = g_pacc + ((size_t)(sp * NBH + bh) * NN + i0) * D;
    #pragma unroll
    for (int mt = 0; mt < MT_W; mt++) {
        int d = mi * (MT_W * 16) + mt * 16 + g;
        #pragma unroll
        for (int ntl = 0; ntl < NT_W; ntl++) {
            int iL = (ni * NT_W + ntl) * 8 + tg * 2;
            pa[iL * D + d]           = acc[mt][ntl][0];
            pa[(iL + 1) * D + d]     = acc[mt][ntl][1];
            pa[iL * D + d + 8]       = acc[mt][ntl][2];
            pa[(iL + 1) * D + d + 8] = acc[mt][ntl][3];
        }
    }
}

// ---------------- 5. combine partials: normalize + ELU + pooling ----------------
template <int D, int S, int NBH>
__global__ __launch_bounds__(256) void k_comb(int outid, int H, int slot) {
    __shared__ float tile[64 * D];
    __shared__ float invs[64];

    int tid = threadIdx.x;
    int bh = blockIdx.y, b = bh / H, head = bh - b * H, hoff = head * D;
    int i0 = blockIdx.x * 64;

    if (tid < 64) {
        float s = 0.f;
        #pragma unroll
        for (int sp = 0; sp < S; sp++)
            s += g_psum[(size_t)(sp * NBH + bh) * NN + i0 + tid];
        invs[tid] = (s > 0.f) ? (1.f / s) : 0.f;
    }
    __syncthreads();

    float* outp = bufsel(outid);
    for (int e = tid; e < 64 * D; e += 256) {
        int r = e / D, d = e - r * D;
        float a = 0.f;
        #pragma unroll
        for (int sp = 0; sp < S; sp++)
            a += g_pacc[((size_t)(sp * NBH + bh) * NN + i0) * D + e];
        float o = eluf(a * invs[r]);
        tile[e] = o;
        outp[(size_t)(b * NN + i0 + r) * HIDD + hoff + d] = o;
    }
    __syncthreads();

    if (tid < D) {
        float s = 0.f;
        #pragma unroll 8
        for (int r = 0; r < 64; r++) s += tile[r * D + tid];
        g_poolc[((slot * 16 + blockIdx.x) * BB + b) * HIDD + hoff + tid] = s;
    }
}

// ---------------- 6. gate MLP ----------------
__global__ void k_gates(const float* __restrict__ w1, const float* __restrict__ b1,
                        const float* __restrict__ w2, const float* __restrict__ b2)
{
    __shared__ float pool[2 * HIDD];
    __shared__ float hid[48];
    int b = blockIdx.x, tid = threadIdx.x;
    if (tid < 192) {
        int slot = tid < 96 ? 0 : 1;
        int col = tid < 96 ? tid : tid - 96;
        float s = 0.f;
        #pragma unroll
        for (int c = 0; c < 16; c++) s += g_poolc[((slot * 16 + c) * BB + b) * HIDD + col];
        pool[tid] = s * (1.f / NN);
    }
    __syncthreads();
    if (tid < 48) {
        float s = b1[tid];
        #pragma unroll 4
        for (int d = 0; d < 192; d++) s += pool[d] * w1[d * 48 + tid];
        hid[tid] = eluf(s);
    }
    __syncthreads();
    if (tid < 2) {
        float s = b2[tid];
        #pragma unroll
        for (int d = 0; d < 48; d++) s += hid[d] * w2[d * 2 + tid];
        g_gates[b * 2 + tid] = 1.f / (1.f + __expf(-s));
    }
}

// ---------------- 7. final projection + output ----------------
__global__ void k_final(const float* __restrict__ proj_w, const float* __restrict__ proj_b,
                        float* __restrict__ out)
{
    __shared__ float gt[288];
    int b = blockIdx.x, tid = threadIdx.x;
    if (tid < 288) {
        int slot = 2 + tid / 96;
        int col = tid % 96;
        float s = 0.f;
        #pragma unroll
        for (int c = 0; c < 16; c++) s += g_poolc[((slot * 16 + c) * BB + b) * HIDD + col];
        gt[tid] = s * (1.f / NN);
    }
    __syncthreads();
    if (tid < 128) {
        float s = proj_b[tid];
        #pragma unroll 4
        for (int d = 0; d < 288; d++) s += gt[d] * proj_w[d * 128 + tid];
        out[b * 128 + tid] = eluf(s);
    }
    if (tid == 128) {
        out[BB * 128 + b]      = g_gates[b * 2];
        out[BB * 128 + BB + b] = g_gates[b * 2 + 1];
    }
}

// ---------------- launch ----------------
extern "C" void kernel_launch(void* const* d_in, const int* in_sizes, int n_in,
                              void* d_out, int out_size)
{
    const float* x      = (const float*)d_in[0];
    const int*   adj    = (const int*)  d_in[1];
    const float* ln_g   = (const float*)d_in[2];
    const float* ln_b   = (const float*)d_in[3];
    const float* pre_w  = (const float*)d_in[4];
    const float* pre_b  = (const float*)d_in[5];
    const float* g1_w   = (const float*)d_in[6];
    const float* g1_as  = (const float*)d_in[7];
    const float* g1_ad  = (const float*)d_in[8];
    const float* g2_w   = (const float*)d_in[9];
    const float* g2_as  = (const float*)d_in[10];
    const float* g2_ad  = (const float*)d_in[11];
    const float* g3_w   = (const float*)d_in[12];
    const float* g3_as  = (const float*)d_in[13];
    const float* g3_ad  = (const float*)d_in[14];
    const float* g4_w   = (const float*)d_in[15];
    const float* g4_as  = (const float*)d_in[16];
    const float* g4_ad  = (const float*)d_in[17];
    const float* g5_w   = (const float*)d_in[18];
    const float* g5_as  = (const float*)d_in[19];
    const float* g5_ad  = (const float*)d_in[20];
    const float* gate_w1= (const float*)d_in[21];
    const float* gate_b1= (const float*)d_in[22];
    const float* gate_w2= (const float*)d_in[23];
    const float* gate_b2= (const float*)d_in[24];
    const float* proj_w = (const float*)d_in[25];
    const float* proj_b = (const float*)d_in[26];
    float* out = (float*)d_out;

    cudaFuncSetAttribute(k_gemmh, cudaFuncAttributeMaxDynamicSharedMemorySize, GH_SMEM);

    k_adjbits<<<4096, 256>>>(adj);
    k_ln_pre<<<BB * NN / 8, 256>>>(x, ln_g, ln_b, pre_w, pre_b);

    // gat1 (x0 -> x1): H=3, D=32; x1 pooled to slot 0
    k_gemmh<<<BB * NN / 64, 256, GH_SMEM>>>(0, 0, 0, 0, 0, g1_w, g1_as, g1_ad, 3);
    k_aggT<32, 2, 24><<<dim3(16, 2, 24), 256>>>(3);
    k_comb<32, 2, 24><<<dim3(16, 24), 256>>>(1, 3, 0);

    // gat2 (x1 -> x2): H=1, D=96; x2 pooled to slot 1
    k_gemmh<<<BB * NN / 64, 256, GH_SMEM>>>(1, 0, 0, 0, 0, g2_w, g2_as, g2_ad, 1);
    k_aggT<96, 4, 8><<<dim3(16, 4, 8), 256>>>(1);
    k_comb<96, 4, 8><<<dim3(16, 8), 256>>>(2, 1, 1);

    k_gates<<<BB, 256>>>(gate_w1, gate_b1, gate_w2, gate_b2);

    // gat4 on td_in = (1-wt)x1 + wt x2 -> x4 (slot 3)
    k_gemmh<<<BB * NN / 64, 256, GH_SMEM>>>(1, 2, 0, 1, 0, g4_w, g4_as, g4_ad, 1);
    k_aggT<96, 4, 8><<<dim3(16, 4, 8), 256>>>(1);
    k_comb<96, 4, 8><<<dim3(16, 8), 256>>>(4, 1, 3);

    // gat5 on ra_in = (1-wr)x1 + wr x2 -> x5 (slot 4)
    k_gemmh<<<BB * NN / 64, 256, GH_SMEM>>>(1, 2, 0, 1, 1, g5_w, g5_as, g5_ad, 1);
    k_aggT<96, 4, 8><<<dim3(16, 4, 8), 256>>>(1);
    k_comb<96, 4, 8><<<dim3(16, 8), 256>>>(5, 1, 4);

    // gat3 on stage_in = x2 + 0.5*(wt x4 + wr x5) -> x3 (slot 2)
    k_gemmh<<<BB * NN / 64, 256, GH_SMEM>>>(2, 4, 5, 2, 0, g3_w, g3_as, g3_ad, 1);
    k_aggT<96, 4, 8><<<dim3(16, 4, 8), 256>>>(1);
    k_comb<96, 4, 8><<<dim3(16, 8), 256>>>(3, 1, 2);

    k_final<<<BB, 288>>>(proj_w, proj_b, out);
}

// round 7
// speedup vs baseline: 1.2232x; 1.2232x over previous
#include <cuda_runtime.h>
#include <cuda_fp16.h>
#include <math.h>
#include <stdint.h>

// ---------------- problem constants ----------------
#define BB   8
#define NN   1024
#define IND  64
#define HIDD 96
#define NEG  0.2f

// ---------------- scratch (device globals) ----------------
__device__ float    g_x[6][BB * NN * HIDD];        // x0..x5
__device__ uint32_t g_hT[BB * HIDD * (NN / 2)];    // h transposed, fp16x2: [b][col][n/2]
__device__ float    g_es[BB * 3 * NN];
__device__ float    g_ed[BB * 3 * NN];
__device__ unsigned g_adjb[NN * NN / 32];
__device__ float    g_gates[BB * 2];
__device__ float    g_poolc[5 * 16 * BB * HIDD];   // [slot][chunk16][b][col]

// ---------------- helpers ----------------
__device__ __forceinline__ float warpSum(float v) {
    #pragma unroll
    for (int o = 16; o; o >>= 1) v += __shfl_xor_sync(0xffffffffu, v, o);
    return v;
}
__device__ __forceinline__ float warpMax(float v) {
    #pragma unroll
    for (int o = 16; o; o >>= 1) v = fmaxf(v, __shfl_xor_sync(0xffffffffu, v, o));
    return v;
}
__device__ __forceinline__ float eluf(float x) { return x > 0.f ? x : expm1f(x); }
__device__ __forceinline__ float* bufsel(int id) { return g_x[id]; }

__device__ __forceinline__ uint32_t to_tf32(float f) {
    uint32_t u;
    asm("cvt.rna.tf32.f32 %0, %1;" : "=r"(u) : "f"(f));
    return u;
}
__device__ __forceinline__ void mma_tf32(float* c, uint32_t a0, uint32_t a1,
                                         uint32_t a2, uint32_t a3,
                                         uint32_t b0, uint32_t b1) {
    asm volatile(
        "mma.sync.aligned.m16n8k8.row.col.f32.tf32.tf32.f32 "
        "{%0,%1,%2,%3}, {%4,%5,%6,%7}, {%8,%9}, {%0,%1,%2,%3};"
        : "+f"(c[0]), "+f"(c[1]), "+f"(c[2]), "+f"(c[3])
        : "r"(a0), "r"(a1), "r"(a2), "r"(a3), "r"(b0), "r"(b1));
}
__device__ __forceinline__ void mma_f16(float* c, uint32_t a0, uint32_t a1,
                                        uint32_t a2, uint32_t a3,
                                        uint32_t b0, uint32_t b1) {
    asm volatile(
        "mma.sync.aligned.m16n8k16.row.col.f32.f16.f16.f32 "
        "{%0,%1,%2,%3}, {%4,%5,%6,%7}, {%8,%9}, {%0,%1,%2,%3};"
        : "+f"(c[0]), "+f"(c[1]), "+f"(c[2]), "+f"(c[3])
        : "r"(a0), "r"(a1), "r"(a2), "r"(a3), "r"(b0), "r"(b1));
}
__device__ __forceinline__ uint32_t pack_h2(float lo, float hi) {
    __half2 h = __floats2half2_rn(lo, hi);
    return *reinterpret_cast<uint32_t*>(&h);
}

// ---------------- 1. adjacency -> bitmask ----------------
__global__ void k_adjbits(const int* __restrict__ adj) {
    int gw   = (blockIdx.x * blockDim.x + threadIdx.x) >> 5;
    int lane = threadIdx.x & 31;
    unsigned m = __ballot_sync(0xffffffffu, adj[gw * 32 + lane] > 0);
    if (lane == 0) g_adjb[gw] = m;
}

// ---------------- 2. LayerNorm + pre Linear + ELU -> x0 ----------------
__global__ __launch_bounds__(256) void k_ln_pre(
    const float* __restrict__ x, const float* __restrict__ ln_g,
    const float* __restrict__ ln_b, const float* __restrict__ W,
    const float* __restrict__ bias)
{
    __shared__ float Ws[IND * HIDD];
    __shared__ float xs[8][IND];
    int tid = threadIdx.x, warp = tid >> 5, lane = tid & 31;
    for (int i = tid; i < IND * HIDD; i += 256) Ws[i] = W[i];

    int row = blockIdx.x * 8 + warp;
    const float* xr = x + row * IND;
    float v0 = xr[lane], v1 = xr[lane + 32];
    float mu = warpSum(v0 + v1) * (1.f / IND);
    float d0 = v0 - mu, d1 = v1 - mu;
    float var = warpSum(d0 * d0 + d1 * d1) * (1.f / IND);
    float rs = rsqrtf(var + 1e-5f);
    xs[warp][lane]      = d0 * rs * ln_g[lane]      + ln_b[lane];
    xs[warp][lane + 32] = d1 * rs * ln_g[lane + 32] + ln_b[lane + 32];
    __syncthreads();

    float a0 = bias[lane], a1 = bias[lane + 32], a2 = bias[lane + 64];
    #pragma unroll
    for (int d = 0; d < IND; d++) {
        float xv = xs[warp][d];
        a0 += xv * Ws[d * HIDD + lane];
        a1 += xv * Ws[d * HIDD + lane + 32];
        a2 += xv * Ws[d * HIDD + lane + 64];
    }
    float* o = g_x[0] + row * HIDD;
    o[lane] = eluf(a0); o[lane + 32] = eluf(a1); o[lane + 64] = eluf(a2);
}

// ---------------- 3. h = mix(x) @ W via tf32 MMA; es/ed; hT(fp16) store ----------------
#define GH_WS   0
#define GH_TILE 39936
#define GH_AV   (39936 + 25600)
#define GH_SMEM (GH_AV + 768)

__global__ __launch_bounds__(256) void k_gemmh(
    int ia, int ib, int ic, int mode, int gidx,
    const float* __restrict__ W, const float* __restrict__ a_src,
    const float* __restrict__ a_dst, int H)
{
    extern __shared__ char dsm[];
    uint32_t* Ws_u  = (uint32_t*)(dsm + GH_WS);
    uint32_t* in_s  = (uint32_t*)(dsm + GH_TILE);
    float*    out_s = (float*)(dsm + GH_TILE);
    float*    as_s  = (float*)(dsm + GH_AV);
    float*    ad_s  = as_s + 96;

    int tid = threadIdx.x, wid = tid >> 5, lane = tid & 31;
    int g = lane >> 2, tg = lane & 3;
    int row0 = blockIdx.x * 64;
    int b = row0 >> 10, nb = row0 & (NN - 1);

    float c_a = 1.f, c_b = 0.f, c_c = 0.f;
    if (mode == 1) { float gg = g_gates[b * 2 + gidx]; c_a = 1.f - gg; c_b = gg; }
    else if (mode == 2) { c_b = 0.5f * g_gates[b * 2]; c_c = 0.5f * g_gates[b * 2 + 1]; }

    for (int i = tid; i < 96 * 96; i += 256) {
        int r = i / 96, c = i - r * 96;
        Ws_u[r * 104 + c] = to_tf32(W[i]);
    }
    if (tid < 96) { as_s[tid] = a_src[tid]; ad_s[tid] = a_dst[tid]; }

    const float* A  = bufsel(ia) + row0 * HIDD;
    const float* Bp = bufsel(ib) + row0 * HIDD;
    const float* Cp = bufsel(ic) + row0 * HIDD;
    for (int idx = tid; idx < 64 * 96; idx += 256) {
        int r = idx / 96, c = idx - r * 96;
        float v = c_a * A[idx];
        if (mode >= 1) v += c_b * Bp[idx];
        if (mode == 2) v += c_c * Cp[idx];
        in_s[r * 100 + c] = to_tf32(v);
    }
    __syncthreads();

    int mrow = (wid >> 1) * 16;
    int n0 = (wid & 1) * 48;
    float acc[6][4];
    #pragma unroll
    for (int nt = 0; nt < 6; nt++)
        #pragma unroll
        for (int q = 0; q < 4; q++) acc[nt][q] = 0.f;

    #pragma unroll
    for (int kt = 0; kt < 12; kt++) {
        int kl = kt * 8 + tg;
        uint32_t a0 = in_s[(mrow + g) * 100 + kl];
        uint32_t a1 = in_s[(mrow + g + 8) * 100 + kl];
        uint32_t a2 = in_s[(mrow + g) * 100 + kl + 4];
        uint32_t a3 = in_s[(mrow + g + 8) * 100 + kl + 4];
        #pragma unroll
        for (int nt = 0; nt < 6; nt++) {
            uint32_t b0 = Ws_u[kl * 104 + n0 + nt * 8 + g];
            uint32_t b1 = Ws_u[(kl + 4) * 104 + n0 + nt * 8 + g];
            mma_tf32(acc[nt], a0, a1, a2, a3, b0, b1);
        }
    }
    __syncthreads();

    #pragma unroll
    for (int nt = 0; nt < 6; nt++) {
        int col = n0 + nt * 8 + tg * 2;
        out_s[(mrow + g) * 97 + col]         = acc[nt][0];
        out_s[(mrow + g) * 97 + col + 1]     = acc[nt][1];
        out_s[(mrow + g + 8) * 97 + col]     = acc[nt][2];
        out_s[(mrow + g + 8) * 97 + col + 1] = acc[nt][3];
    }
    __syncthreads();

    // hT store as fp16 pairs: hTu[d][n/2]
    uint32_t* hTu = g_hT + (size_t)b * HIDD * (NN / 2);
    for (int idx = tid; idx < 96 * 32; idx += 256) {
        int d = idx >> 5, np = idx & 31;
        float lo = out_s[(2 * np) * 97 + d];
        float hi = out_s[(2 * np + 1) * 97 + d];
        hTu[(size_t)d * (NN / 2) + (nb >> 1) + np] = pack_h2(lo, hi);
    }

    #pragma unroll
    for (int rr = 0; rr < 8; rr++) {
        int r = wid * 8 + rr;
        float v0 = out_s[r * 97 + lane];
        float v1 = out_s[r * 97 + 32 + lane];
        float v2 = out_s[r * 97 + 64 + lane];
        float s0v = v0 * as_s[lane], s1v = v1 * as_s[lane + 32], s2v = v2 * as_s[lane + 64];
        float d0v = v0 * ad_s[lane], d1v = v1 * ad_s[lane + 32], d2v = v2 * ad_s[lane + 64];
        int n = nb + r;
        if (H == 1) {
            float ps = warpSum(s0v + s1v + s2v);
            float pd = warpSum(d0v + d1v + d2v);
            if (lane == 0) { g_es[b * NN + n] = ps; g_ed[b * NN + n] = pd; }
        } else {
            float s0 = warpSum(s0v), s1 = warpSum(s1v), s2 = warpSum(s2v);
            float e0 = warpSum(d0v), e1 = warpSum(d1v), e2 = warpSum(d2v);
            if (lane == 0) {
                g_es[(b * 3 + 0) * NN + n] = s0; g_ed[(b * 3 + 0) * NN + n] = e0;
                g_es[(b * 3 + 1) * NN + n] = s1; g_ed[(b * 3 + 1) * NN + n] = e1;
                g_es[(b * 3 + 2) * NN + n] = s2; g_ed[(b * 3 + 2) * NN + n] = e2;
            }
        }
    }
}

// ---------------- 4. attention aggregation (fp16 mma, warp-owns-8-i) ----------------
// out^T[D x 64] per block; warp w owns rows i0+w*8..+7 and the full D.
// Weight computed once per (i,j); B fragment packed in registers.
// grid (16, B*H), 256 threads.
template <int D>
__global__ __launch_bounds__(256) void k_aggf(int outid, int H, int slot) {
    constexpr int MT = D / 16;
    constexpr int HS = 20;             // uint stride per d row (conflict-free)

    __shared__ uint32_t hs[D * HS];
    __shared__ float eds[32], e1s[32], e2s[32];
    __shared__ unsigned ms[64];
    __shared__ float red[8];
    __shared__ float rsums[64], invs[64];
    __shared__ float pools_s[D * 8];

    int tid = threadIdx.x, wid = tid >> 5, lane = tid & 31;
    int g = lane >> 2, tg = lane & 3;
    int bh = blockIdx.y, b = bh / H, head = bh - b * H, hoff = head * D;
    int i0 = blockIdx.x * 64;
    int base_i = wid * 8;
    int i = i0 + base_i + g;

    const uint32_t* hTu = g_hT + ((size_t)b * HIDD + hoff) * (NN / 2);

    // global ed max for this bh
    {
        const float4* ed4 = (const float4*)(g_ed + bh * NN);
        float4 vv = ed4[tid];
        float mx = fmaxf(fmaxf(vv.x, vv.y), fmaxf(vv.z, vv.w));
        mx = warpMax(mx);
        if (lane == 0) red[wid] = mx;
    }
    __syncthreads();
    float maxed = fmaxf(fmaxf(fmaxf(red[0], red[1]), fmaxf(red[2], red[3])),
                        fmaxf(fmaxf(red[4], red[5]), fmaxf(red[6], red[7])));

    float es_i = g_es[bh * NN + i];
    float A1, A2;
    {
        float t = es_i + maxed;
        float m = t > 0.f ? t : NEG * t;
        A1 = __expf(t - m);
        A2 = __expf(NEG * t - m);
    }
    float rs = 0.f;

    float acc[MT][4];
    #pragma unroll
    for (int mt = 0; mt < MT; mt++)
        #pragma unroll
        for (int q = 0; q < 4; q++) acc[mt][q] = 0.f;

    for (int c = 0; c < NN / 32; c++) {
        __syncthreads();
        #pragma unroll
        for (int it = 0; it < D * 16 / 256; it++) {
            int idx = tid + it * 256;
            int d = idx >> 4, u = idx & 15;
            hs[d * HS + u] = hTu[(size_t)d * (NN / 2) + c * 16 + u];
        }
        if (tid < 32) {
            float e = g_ed[bh * NN + c * 32 + tid];
            eds[tid] = e;
            float dd = e - maxed;
            e1s[tid] = __expf(dd);
            e2s[tid] = __expf(NEG * dd);
        } else if (tid >= 96 && tid < 160) {
            ms[tid - 96] = g_adjb[(i0 + tid - 96) * 32 + c];
        }
        __syncthreads();

        unsigned msb = ms[base_i + g];

        #pragma unroll
        for (int kt = 0; kt < 2; kt++) {
            int j0 = kt * 16 + 2 * tg;   // local j of first weight
            float w00, w01, w10, w11;
            {
                int j = j0;
                float t = es_i + eds[j];
                float w = (t > 0.f) ? A1 * e1s[j] : A2 * e2s[j];
                w00 = ((msb >> j) & 1u) ? w : 0.f;
                j = j0 + 1;
                t = es_i + eds[j];
                w = (t > 0.f) ? A1 * e1s[j] : A2 * e2s[j];
                w01 = ((msb >> j) & 1u) ? w : 0.f;
                j = j0 + 8;
                t = es_i + eds[j];
                w = (t > 0.f) ? A1 * e1s[j] : A2 * e2s[j];
                w10 = ((msb >> j) & 1u) ? w : 0.f;
                j = j0 + 9;
                t = es_i + eds[j];
                w = (t > 0.f) ? A1 * e1s[j] : A2 * e2s[j];
                w11 = ((msb >> j) & 1u) ? w : 0.f;
            }
            rs += (w00 + w01) + (w10 + w11);
            uint32_t b0 = pack_h2(w00, w01);
            uint32_t b1 = pack_h2(w10, w11);

            #pragma unroll
            for (int mt = 0; mt < MT; mt++) {
                int dlo = mt * 16 + g, dhi = dlo + 8;
                uint32_t a0 = hs[dlo * HS + kt * 8 + tg];
                uint32_t a1 = hs[dhi * HS + kt * 8 + tg];
                uint32_t a2 = hs[dlo * HS + kt * 8 + tg + 4];
                uint32_t a3 = hs[dhi * HS + kt * 8 + tg + 4];
                mma_f16(acc[mt], a0, a1, a2, a3, b0, b1);
            }
        }
    }

    // row sums: reduce over tg
    rs += __shfl_xor_sync(0xffffffffu, rs, 1);
    rs += __shfl_xor_sync(0xffffffffu, rs, 2);
    if (tg == 0) rsums[base_i + g] = rs;
    __syncthreads();
    if (tid < 64) {
        float rv = rsums[tid];
        invs[tid] = (rv > 0.f) ? (1.f / rv) : 0.f;
    }
    __syncthreads();

    // epilogue: normalize + ELU + store + pooling
    float* outp = bufsel(outid);
    int iA = base_i + 2 * tg, iB = iA + 1;
    float invA = invs[iA], invB = invs[iB];
    size_t rowA = (size_t)(b * NN + i0 + iA) * HIDD + hoff;
    size_t rowB = rowA + HIDD;

    #pragma unroll
    for (int mt = 0; mt < MT; mt++) {
        int dlo = mt * 16 + g, dhi = dlo + 8;
        float o0 = eluf(acc[mt][0] * invA);
        float o1 = eluf(acc[mt][1] * invB);
        float o2 = eluf(acc[mt][2] * invA);
        float o3 = eluf(acc[mt][3] * invB);
        outp[rowA + dlo] = o0;
        outp[rowB + dlo] = o1;
        outp[rowA + dhi] = o2;
        outp[rowB + dhi] = o3;
        float plo = o0 + o1, phi = o2 + o3;
        plo += __shfl_xor_sync(0xffffffffu, plo, 1);
        plo += __shfl_xor_sync(0xffffffffu, plo, 2);
        phi += __shfl_xor_sync(0xffffffffu, phi, 1);
        phi += __shfl_xor_sync(0xffffffffu, phi, 2);
        if (tg == 0) {
            pools_s[dlo * 8 + wid] = plo;
            pools_s[dhi * 8 + wid] = phi;
        }
    }
    __syncthreads();
    if (tid < D) {
        const float* p = pools_s + tid * 8;
        float s = (p[0] + p[1]) + (p[2] + p[3]) + (p[4] + p[5]) + (p[6] + p[7]);
        g_poolc[((slot * 16 + blockIdx.x) * BB + b) * HIDD + hoff + tid] = s;
    }
}

// ---------------- 5. gate MLP ----------------
__global__ void k_gates(const float* __restrict__ w1, const float* __restrict__ b1,
                        const float* __restrict__ w2, const float* __restrict__ b2)
{
    __shared__ float pool[2 * HIDD];
    __shared__ float hid[48];
    int b = blockIdx.x, tid = threadIdx.x;
    if (tid < 192) {
        int slot = tid < 96 ? 0 : 1;
        int col = tid < 96 ? tid : tid - 96;
        float s = 0.f;
        #pragma unroll
        for (int c = 0; c < 16; c++) s += g_poolc[((slot * 16 + c) * BB + b) * HIDD + col];
        pool[tid] = s * (1.f / NN);
    }
    __syncthreads();
    if (tid < 48) {
        float s = b1[tid];
        #pragma unroll 4
        for (int d = 0; d < 192; d++) s += pool[d] * w1[d * 48 + tid];
        hid[tid] = eluf(s);
    }
    __syncthreads();
    if (tid < 2) {
        float s = b2[tid];
        #pragma unroll
        for (int d = 0; d < 48; d++) s += hid[d] * w2[d * 2 + tid];
        g_gates[b * 2 + tid] = 1.f / (1.f + __expf(-s));
    }
}

// ---------------- 6. final projection + output ----------------
__global__ void k_final(const float* __restrict__ proj_w, const float* __restrict__ proj_b,
                        float* __restrict__ out)
{
    __shared__ float gt[288];
    int b = blockIdx.x, tid = threadIdx.x;
    if (tid < 288) {
        int slot = 2 + tid / 96;
        int col = tid % 96;
        float s = 0.f;
        #pragma unroll
        for (int c = 0; c < 16; c++) s += g_poolc[((slot * 16 + c) * BB + b) * HIDD + col];
        gt[tid] = s * (1.f / NN);
    }
    __syncthreads();
    if (tid < 128) {
        float s = proj_b[tid];
        #pragma unroll 4
        for (int d = 0; d < 288; d++) s += gt[d] * proj_w[d * 128 + tid];
        out[b * 128 + tid] = eluf(s);
    }
    if (tid == 128) {
        out[BB * 128 + b]      = g_gates[b * 2];
        out[BB * 128 + BB + b] = g_gates[b * 2 + 1];
    }
}

// ---------------- launch ----------------
extern "C" void kernel_launch(void* const* d_in, const int* in_sizes, int n_in,
                              void* d_out, int out_size)
{
    const float* x      = (const float*)d_in[0];
    const int*   adj    = (const int*)  d_in[1];
    const float* ln_g   = (const float*)d_in[2];
    const float* ln_b   = (const float*)d_in[3];
    const float* pre_w  = (const float*)d_in[4];
    const float* pre_b  = (const float*)d_in[5];
    const float* g1_w   = (const float*)d_in[6];
    const float* g1_as  = (const float*)d_in[7];
    const float* g1_ad  = (const float*)d_in[8];
    const float* g2_w   = (const float*)d_in[9];
    const float* g2_as  = (const float*)d_in[10];
    const float* g2_ad  = (const float*)d_in[11];
    const float* g3_w   = (const float*)d_in[12];
    const float* g3_as  = (const float*)d_in[13];
    const float* g3_ad  = (const float*)d_in[14];
    const float* g4_w   = (const float*)d_in[15];
    const float* g4_as  = (const float*)d_in[16];
    const float* g4_ad  = (const float*)d_in[17];
    const float* g5_w   = (const float*)d_in[18];
    const float* g5_as  = (const float*)d_in[19];
    const float* g5_ad  = (const float*)d_in[20];
    const float* gate_w1= (const float*)d_in[21];
    const float* gate_b1= (const float*)d_in[22];
    const float* gate_w2= (const float*)d_in[23];
    const float* gate_b2= (const float*)d_in[24];
    const float* proj_w = (const float*)d_in[25];
    const float* proj_b = (const float*)d_in[26];
    float* out = (float*)d_out;

    cudaFuncSetAttribute(k_gemmh, cudaFuncAttributeMaxDynamicSharedMemorySize, GH_SMEM);

    k_adjbits<<<4096, 256>>>(adj);
    k_ln_pre<<<BB * NN / 8, 256>>>(x, ln_g, ln_b, pre_w, pre_b);

    // gat1 (x0 -> x1): H=3, D=32; x1 pooled to slot 0
    k_gemmh<<<BB * NN / 64, 256, GH_SMEM>>>(0, 0, 0, 0, 0, g1_w, g1_as, g1_ad, 3);
    k_aggf<32><<<dim3(16, BB * 3), 256>>>(1, 3, 0);

    // gat2 (x1 -> x2): H=1, D=96; x2 pooled to slot 1
    k_gemmh<<<BB * NN / 64, 256, GH_SMEM>>>(1, 0, 0, 0, 0, g2_w, g2_as, g2_ad, 1);
    k_aggf<96><<<dim3(16, BB), 256>>>(2, 1, 1);

    k_gates<<<BB, 256>>>(gate_w1, gate_b1, gate_w2, gate_b2);

    // gat4 on td_in = (1-wt)x1 + wt x2 -> x4 (slot 3)
    k_gemmh<<<BB * NN / 64, 256, GH_SMEM>>>(1, 2, 0, 1, 0, g4_w, g4_as, g4_ad, 1);
    k_aggf<96><<<dim3(16, BB), 256>>>(4, 1, 3);

    // gat5 on ra_in = (1-wr)x1 + wr x2 -> x5 (slot 4)
    k_gemmh<<<BB * NN / 64, 256, GH_SMEM>>>(1, 2, 0, 1, 1, g5_w, g5_as, g5_ad, 1);
    k_aggf<96><<<dim3(16, BB), 256>>>(5, 1, 4);

    // gat3 on stage_in = x2 + 0.5*(wt x4 + wr x5) -> x3 (slot 2)
    k_gemmh<<<BB * NN / 64, 256, GH_SMEM>>>(2, 4, 5, 2, 0, g3_w, g3_as, g3_ad, 1);
    k_aggf<96><<<dim3(16, BB), 256>>>(3, 1, 2);

    k_final<<<BB, 288>>>(proj_w, proj_b, out);
}